// round 11
// baseline (speedup 1.0000x reference)
#include <cuda_runtime.h>

#define N_NODES 100000
#define N_EDGES 1600000
#define F 64
#define TWOF 128
#define TILE_N 32

// ---------------------------------------------------------------------------
// Scratch (device globals; allocations are forbidden)
// ---------------------------------------------------------------------------
__device__ int    g_is32;                // 1 if src/dst are int32, 0 if int64
__device__ int    g_deg[N_NODES];        // per-node in-degree
__device__ int    g_off[N_NODES];        // CSR exclusive offsets
__device__ int    g_cursor[N_NODES];     // fill cursors (seeded = g_off by scan)
__device__ int    g_esrc[N_EDGES];       // bucketed source-node ids (CSR adj)
__device__ float4 g_hN[(size_t)N_NODES * 16];  // mean-aggregated features [N,64]

// Index load that works for either dtype.
__device__ __forceinline__ int load_id(const void* p, int e, int is32) {
    return is32 ? ((const int*)p)[e] : (int)((const long long*)p)[e];
}

// ---------------------------------------------------------------------------
// 1) zero degree counters + dtype detection.
//    Probe: OR the "high words" of the first 2048 int64-interpreted elements
//    (int32 indexes 2i+1 < 4096 <= N_EDGES: in-bounds under either dtype).
//    All-zero -> genuine int64 (node ids < 2^31 so high words are 0);
//    any nonzero -> buffer is int32 (those words are real node ids).
//    Deterministic for fixed inputs -> graph-replay safe.
// ---------------------------------------------------------------------------
__global__ void zero_kernel(const void* __restrict__ srcbuf) {
    int stride = gridDim.x * blockDim.x;
    for (int i = blockIdx.x * blockDim.x + threadIdx.x; i < N_NODES; i += stride)
        g_deg[i] = 0;

    if (blockIdx.x == 0 && threadIdx.x < 32) {
        const int* p = (const int*)srcbuf;
        int acc = 0;
        for (int i = threadIdx.x; i < 2048; i += 32)
            acc |= __ldg(p + 2 * i + 1);
#pragma unroll
        for (int d = 16; d > 0; d >>= 1)
            acc |= __shfl_xor_sync(0xffffffffu, acc, d);
        if (threadIdx.x == 0) g_is32 = (acc != 0) ? 1 : 0;
    }
}

// ---------------------------------------------------------------------------
// 2) degree histogram (grid-stride; guarded: bad ids dropped, not crashed)
// ---------------------------------------------------------------------------
__global__ __launch_bounds__(256) void hist_kernel(const void* __restrict__ dst) {
    const int is32 = g_is32;
    const int stride = gridDim.x * blockDim.x;
    for (int e = blockIdx.x * blockDim.x + threadIdx.x; e < N_EDGES; e += stride) {
        int d = load_id(dst, e, is32);
        if ((unsigned)d < N_NODES) atomicAdd(&g_deg[d], 1);
    }
}

// ---------------------------------------------------------------------------
// 3) exclusive scan of degrees -> offsets + cursor seed. One block,
//    1024 threads: serial 98-element chunk sums, Hillis-Steele across the
//    1024 partials, per-chunk offset emission. Seeds g_cursor = g_off so
//    the fill kernel's atomic returns an absolute write address.
// ---------------------------------------------------------------------------
__global__ void scan_kernel() {
    __shared__ int s[1024];
    const int CH = (N_NODES + 1023) / 1024;  // 98
    int t = threadIdx.x;
    int base = t * CH;

    int sum = 0;
#pragma unroll 4
    for (int k = 0; k < CH; k++) {
        int idx = base + k;
        if (idx < N_NODES) sum += g_deg[idx];
    }
    s[t] = sum;
    __syncthreads();

    for (int d = 1; d < 1024; d <<= 1) {
        int v = (t >= d) ? s[t - d] : 0;
        __syncthreads();
        s[t] += v;
        __syncthreads();
    }

    int run = (t == 0) ? 0 : s[t - 1];  // exclusive prefix of this chunk
#pragma unroll 4
    for (int k = 0; k < CH; k++) {
        int idx = base + k;
        if (idx < N_NODES) {
            g_off[idx] = run;
            g_cursor[idx] = run;
            run += g_deg[idx];
        }
    }
}

// ---------------------------------------------------------------------------
// 4) bucket fill: group src ids by destination. Cursor atomic returns the
//    absolute CSR slot directly (no g_off load on the critical path).
// ---------------------------------------------------------------------------
__global__ __launch_bounds__(256) void fill_kernel(const void* __restrict__ src,
                                                   const void* __restrict__ dst) {
    const int is32 = g_is32;
    const int stride = gridDim.x * blockDim.x;
    for (int e = blockIdx.x * blockDim.x + threadIdx.x; e < N_EDGES; e += stride) {
        int d = load_id(dst, e, is32);
        int sv = load_id(src, e, is32);
        if ((unsigned)d >= N_NODES || (unsigned)sv >= N_NODES) continue;
        int pos = atomicAdd(&g_cursor[d], 1);
        g_esrc[pos] = sv;
    }
}

// ---------------------------------------------------------------------------
// 5) pull aggregation: warp per node. Each lane owns 2 columns (float2).
//    8-edge unroll (avg degree = 16) for deep MLP; each edge's h-row read
//    is a fully coalesced 256B transaction (h is L2-resident at 25.6MB).
// ---------------------------------------------------------------------------
__global__ __launch_bounds__(256) void aggregate_kernel(const float* __restrict__ h) {
    int node = (blockIdx.x * blockDim.x + threadIdx.x) >> 5;
    if (node >= N_NODES) return;
    int lane = threadIdx.x & 31;

    int off = g_off[node];
    int deg = g_deg[node];
    const float2* h2 = reinterpret_cast<const float2*>(h);

    float ax = 0.f, ay = 0.f;
    int i = 0;
    for (; i + 8 <= deg; i += 8) {
        int s[8];
#pragma unroll
        for (int u = 0; u < 8; u++) s[u] = __ldg(g_esrc + off + i + u);
        float2 v[8];
#pragma unroll
        for (int u = 0; u < 8; u++) v[u] = __ldg(h2 + s[u] * 32 + lane);
#pragma unroll
        for (int u = 0; u < 8; u++) { ax += v[u].x; ay += v[u].y; }
    }
    for (; i < deg; i++) {
        int s0 = __ldg(g_esrc + off + i);
        float2 v0 = __ldg(h2 + s0 * 32 + lane);
        ax += v0.x;
        ay += v0.y;
    }

    float inv = 1.0f / (float)max(deg, 1);
    float2 r; r.x = ax * inv; r.y = ay * inv;
    reinterpret_cast<float2*>(g_hN)[node * 32 + lane] = r;
}

// ---------------------------------------------------------------------------
// 6) fused concat + GEMM + bias.
//    out[n][j] = sum_k [h(n) | hN(n)][k] * W[j][k] + b[j]
//    128 threads/block; each thread computes 4 nodes x 4 outs with float4
//    smem loads -> 2 smem-B per FMA (128B/cyc crossbar vs 64 FMA/cyc
//    balance point). Smem 48KB static: sH 32x128 + sW 64x128 (XOR-swizzled).
// ---------------------------------------------------------------------------
__global__ __launch_bounds__(128) void gemm_kernel(
    const float* __restrict__ h,
    const float* __restrict__ W,
    const float* __restrict__ b,
    float* __restrict__ out) {
    __shared__ float sH[TILE_N * TWOF];
    __shared__ float sW[64 * TWOF];

    int t = threadIdx.x;
    int node0 = blockIdx.x * TILE_N;

    // W tile (64x32 float4), swizzled: chunk c = k4 ^ (j & 7)
    for (int idx = t; idx < 64 * 32; idx += 128) {
        int j = idx >> 5, k4 = idx & 31;
        float4 w = __ldg(reinterpret_cast<const float4*>(W) + j * 32 + k4);
        reinterpret_cast<float4*>(sW + j * TWOF)[k4 ^ (j & 7)] = w;
    }

    // node rows: [h(64) | hN(64)]
    for (int idx = t; idx < TILE_N * 32; idx += 128) {
        int r = idx >> 5, k4 = idx & 31;
        int n = node0 + r;
        float4 v = make_float4(0.f, 0.f, 0.f, 0.f);
        if (n < N_NODES) {
            if (k4 < 16)
                v = __ldg(reinterpret_cast<const float4*>(h) + n * 16 + k4);
            else
                v = g_hN[(size_t)n * 16 + (k4 - 16)];
        }
        reinterpret_cast<float4*>(sH + r * TWOF)[k4] = v;
    }
    __syncthreads();

    int jl = t & 15;
    int r0 = (t >> 4) * 4;
    int cxor = jl & 7;

    float acc[4][4];
#pragma unroll
    for (int rr = 0; rr < 4; rr++)
#pragma unroll
        for (int jj = 0; jj < 4; jj++) acc[rr][jj] = 0.f;

#pragma unroll
    for (int k4 = 0; k4 < 32; k4++) {
        float4 hv[4], wv[4];
#pragma unroll
        for (int rr = 0; rr < 4; rr++)
            hv[rr] = reinterpret_cast<const float4*>(sH + (r0 + rr) * TWOF)[k4];
        int c = k4 ^ cxor;
#pragma unroll
        for (int jj = 0; jj < 4; jj++)
            wv[jj] = reinterpret_cast<const float4*>(sW + (jl + jj * 16) * TWOF)[c];
#pragma unroll
        for (int rr = 0; rr < 4; rr++)
#pragma unroll
            for (int jj = 0; jj < 4; jj++)
                acc[rr][jj] += hv[rr].x * wv[jj].x + hv[rr].y * wv[jj].y
                             + hv[rr].z * wv[jj].z + hv[rr].w * wv[jj].w;
    }

#pragma unroll
    for (int rr = 0; rr < 4; rr++) {
        int n = node0 + r0 + rr;
        if (n < N_NODES) {
#pragma unroll
            for (int jj = 0; jj < 4; jj++) {
                int j = jl + jj * 16;
                out[(size_t)n * F + j] = acc[rr][jj] + __ldg(b + j);
            }
        }
    }
}

// ---------------------------------------------------------------------------
// inputs (metadata order): h f32[100000,64], src [1.6M] (i32 or i64),
//                          dst [1.6M] (i32 or i64), W f32[64,128], b f32[64]
// output f32[100000,64]
// ---------------------------------------------------------------------------
extern "C" void kernel_launch(void* const* d_in, const int* in_sizes, int n_in,
                              void* d_out, int out_size) {
    const float* h = (const float*)d_in[0];
    const void* src = d_in[1];
    const void* dst = d_in[2];
    const float* W = (const float*)d_in[3];
    const float* b = (const float*)d_in[4];
    float* out = (float*)d_out;

    const int EB = (N_EDGES + 255) / 256;  // 6250

    zero_kernel<<<256, 256>>>(src);
    hist_kernel<<<EB, 256>>>(dst);
    scan_kernel<<<1, 1024>>>();
    fill_kernel<<<EB, 256>>>(src, dst);
    aggregate_kernel<<<(N_NODES * 32 + 255) / 256, 256>>>(h);
    gemm_kernel<<<(N_NODES + TILE_N - 1) / TILE_N, 128>>>(h, W, b, out);
}

// round 13
// speedup vs baseline: 2.0484x; 2.0484x over previous
#include <cuda_runtime.h>

#define N_NODES 100000
#define N_EDGES 1600000
#define F 64
#define TWOF 128
#define TILE_N 32
#define NB_SCAN ((N_NODES + 255) / 256)   // 391 scan blocks

// ---------------------------------------------------------------------------
// Scratch (device globals; allocations are forbidden)
// ---------------------------------------------------------------------------
__device__ int    g_is32;                // 1 if src/dst are int32, 0 if int64
__device__ int    g_deg[N_NODES];        // per-node in-degree
__device__ int    g_off[N_NODES];        // CSR exclusive offsets
__device__ int    g_cursor[N_NODES];     // fill cursors (seeded = g_off)
__device__ int    g_part[NB_SCAN];       // per-block scan partials
__device__ int    g_esrc[N_EDGES];       // bucketed source-node ids (CSR adj)
__device__ float4 g_hN[(size_t)N_NODES * 16];  // mean-aggregated features [N,64]

// Index load that works for either dtype.
__device__ __forceinline__ int load_id(const void* p, int e, int is32) {
    return is32 ? ((const int*)p)[e] : (int)((const long long*)p)[e];
}

// ---------------------------------------------------------------------------
// 1) zero degree counters + dtype detection (validated R11: rel_err 2.8e-7).
//    Probe: OR high words of first 2048 int64-interpreted elements; indexes
//    in-bounds under either dtype; deterministic -> graph-replay safe.
// ---------------------------------------------------------------------------
__global__ void zero_kernel(const void* __restrict__ srcbuf) {
    int stride = gridDim.x * blockDim.x;
    for (int i = blockIdx.x * blockDim.x + threadIdx.x; i < N_NODES; i += stride)
        g_deg[i] = 0;

    if (blockIdx.x == 0 && threadIdx.x < 32) {
        const int* p = (const int*)srcbuf;
        int acc = 0;
        for (int i = threadIdx.x; i < 2048; i += 32)
            acc |= __ldg(p + 2 * i + 1);
#pragma unroll
        for (int d = 16; d > 0; d >>= 1)
            acc |= __shfl_xor_sync(0xffffffffu, acc, d);
        if (threadIdx.x == 0) g_is32 = (acc != 0) ? 1 : 0;
    }
}

// ---------------------------------------------------------------------------
// 2) degree histogram (grid-stride; guarded)
// ---------------------------------------------------------------------------
__global__ __launch_bounds__(256) void hist_kernel(const void* __restrict__ dst) {
    const int is32 = g_is32;
    const int stride = gridDim.x * blockDim.x;
    for (int e = blockIdx.x * blockDim.x + threadIdx.x; e < N_EDGES; e += stride) {
        int d = load_id(dst, e, is32);
        if ((unsigned)d < N_NODES) atomicAdd(&g_deg[d], 1);
    }
}

// ---------------------------------------------------------------------------
// 3a) multi-block scan, phase 1: block-local exclusive scan of 256 degrees.
//     Writes local prefix to g_off, block total to g_part. Full-chip parallel
//     (replaces the single-SM scan suspected to dominate R11's 303us).
// ---------------------------------------------------------------------------
__global__ __launch_bounds__(256) void scan1_kernel() {
    __shared__ int s[256];
    int t = threadIdx.x;
    int i = blockIdx.x * 256 + t;
    int v = (i < N_NODES) ? g_deg[i] : 0;
    s[t] = v;
    __syncthreads();
#pragma unroll
    for (int d = 1; d < 256; d <<= 1) {
        int x = (t >= d) ? s[t - d] : 0;
        __syncthreads();
        s[t] += x;
        __syncthreads();
    }
    if (i < N_NODES) g_off[i] = s[t] - v;       // exclusive local prefix
    if (t == 255) g_part[blockIdx.x] = s[255];  // block total
}

// ---------------------------------------------------------------------------
// 3b) phase 2: exclusive scan of the 391 block partials (one tiny block).
// ---------------------------------------------------------------------------
__global__ __launch_bounds__(512) void scan2_kernel() {
    __shared__ int s[512];
    int t = threadIdx.x;
    int v = (t < NB_SCAN) ? g_part[t] : 0;
    s[t] = v;
    __syncthreads();
#pragma unroll
    for (int d = 1; d < 512; d <<= 1) {
        int x = (t >= d) ? s[t - d] : 0;
        __syncthreads();
        s[t] += x;
        __syncthreads();
    }
    if (t < NB_SCAN) g_part[t] = s[t] - v;      // exclusive
}

// ---------------------------------------------------------------------------
// 3c) phase 3: add block base; emit final offsets + cursor seed.
// ---------------------------------------------------------------------------
__global__ __launch_bounds__(256) void scan3_kernel() {
    int i = blockIdx.x * 256 + threadIdx.x;
    if (i < N_NODES) {
        int off = g_off[i] + g_part[blockIdx.x];
        g_off[i] = off;
        g_cursor[i] = off;
    }
}

// ---------------------------------------------------------------------------
// 4) bucket fill: group src ids by destination. Cursor atomic returns the
//    absolute CSR slot directly. (R11 measured: 25.2us, L2-atomic bound.)
// ---------------------------------------------------------------------------
__global__ __launch_bounds__(256) void fill_kernel(const void* __restrict__ src,
                                                   const void* __restrict__ dst) {
    const int is32 = g_is32;
    const int stride = gridDim.x * blockDim.x;
    for (int e = blockIdx.x * blockDim.x + threadIdx.x; e < N_EDGES; e += stride) {
        int d = load_id(dst, e, is32);
        int sv = load_id(src, e, is32);
        if ((unsigned)d >= N_NODES || (unsigned)sv >= N_NODES) continue;
        int pos = atomicAdd(&g_cursor[d], 1);
        g_esrc[pos] = sv;
    }
}

// ---------------------------------------------------------------------------
// 5) pull aggregation: warp per node. Each lane owns 2 columns (float2).
//    8-edge unroll (avg degree = 16) for deep MLP; each edge's h-row read
//    is a fully coalesced 256B transaction (h is L2-resident at 25.6MB).
// ---------------------------------------------------------------------------
__global__ __launch_bounds__(256) void aggregate_kernel(const float* __restrict__ h) {
    int node = (blockIdx.x * blockDim.x + threadIdx.x) >> 5;
    if (node >= N_NODES) return;
    int lane = threadIdx.x & 31;

    int off = g_off[node];
    int deg = g_deg[node];
    const float2* h2 = reinterpret_cast<const float2*>(h);

    float ax = 0.f, ay = 0.f;
    int i = 0;
    for (; i + 8 <= deg; i += 8) {
        int s[8];
#pragma unroll
        for (int u = 0; u < 8; u++) s[u] = __ldg(g_esrc + off + i + u);
        float2 v[8];
#pragma unroll
        for (int u = 0; u < 8; u++) v[u] = __ldg(h2 + s[u] * 32 + lane);
#pragma unroll
        for (int u = 0; u < 8; u++) { ax += v[u].x; ay += v[u].y; }
    }
    for (; i < deg; i++) {
        int s0 = __ldg(g_esrc + off + i);
        float2 v0 = __ldg(h2 + s0 * 32 + lane);
        ax += v0.x;
        ay += v0.y;
    }

    float inv = 1.0f / (float)max(deg, 1);
    float2 r; r.x = ax * inv; r.y = ay * inv;
    reinterpret_cast<float2*>(g_hN)[node * 32 + lane] = r;
}

// ---------------------------------------------------------------------------
// 6) fused concat + GEMM + bias.
//    out[n][j] = sum_k [h(n) | hN(n)][k] * W[j][k] + b[j]
//    128 threads/block; each thread computes 4 nodes x 4 outs with float4
//    smem loads -> 2 smem-B per FMA (crossbar/FMA balance point).
//    Smem 48KB static: sH 32x128 + sW 64x128 (XOR chunk-swizzled).
// ---------------------------------------------------------------------------
__global__ __launch_bounds__(128) void gemm_kernel(
    const float* __restrict__ h,
    const float* __restrict__ W,
    const float* __restrict__ b,
    float* __restrict__ out) {
    __shared__ float sH[TILE_N * TWOF];
    __shared__ float sW[64 * TWOF];

    int t = threadIdx.x;
    int node0 = blockIdx.x * TILE_N;

    // W tile (64x32 float4), swizzled: chunk c = k4 ^ (j & 7)
    for (int idx = t; idx < 64 * 32; idx += 128) {
        int j = idx >> 5, k4 = idx & 31;
        float4 w = __ldg(reinterpret_cast<const float4*>(W) + j * 32 + k4);
        reinterpret_cast<float4*>(sW + j * TWOF)[k4 ^ (j & 7)] = w;
    }

    // node rows: [h(64) | hN(64)]
    for (int idx = t; idx < TILE_N * 32; idx += 128) {
        int r = idx >> 5, k4 = idx & 31;
        int n = node0 + r;
        float4 v = make_float4(0.f, 0.f, 0.f, 0.f);
        if (n < N_NODES) {
            if (k4 < 16)
                v = __ldg(reinterpret_cast<const float4*>(h) + n * 16 + k4);
            else
                v = g_hN[(size_t)n * 16 + (k4 - 16)];
        }
        reinterpret_cast<float4*>(sH + r * TWOF)[k4] = v;
    }
    __syncthreads();

    int jl = t & 15;
    int r0 = (t >> 4) * 4;
    int cxor = jl & 7;

    float acc[4][4];
#pragma unroll
    for (int rr = 0; rr < 4; rr++)
#pragma unroll
        for (int jj = 0; jj < 4; jj++) acc[rr][jj] = 0.f;

#pragma unroll
    for (int k4 = 0; k4 < 32; k4++) {
        float4 hv[4], wv[4];
#pragma unroll
        for (int rr = 0; rr < 4; rr++)
            hv[rr] = reinterpret_cast<const float4*>(sH + (r0 + rr) * TWOF)[k4];
        int c = k4 ^ cxor;
#pragma unroll
        for (int jj = 0; jj < 4; jj++)
            wv[jj] = reinterpret_cast<const float4*>(sW + (jl + jj * 16) * TWOF)[c];
#pragma unroll
        for (int rr = 0; rr < 4; rr++)
#pragma unroll
            for (int jj = 0; jj < 4; jj++)
                acc[rr][jj] += hv[rr].x * wv[jj].x + hv[rr].y * wv[jj].y
                             + hv[rr].z * wv[jj].z + hv[rr].w * wv[jj].w;
    }

#pragma unroll
    for (int rr = 0; rr < 4; rr++) {
        int n = node0 + r0 + rr;
        if (n < N_NODES) {
#pragma unroll
            for (int jj = 0; jj < 4; jj++) {
                int j = jl + jj * 16;
                out[(size_t)n * F + j] = acc[rr][jj] + __ldg(b + j);
            }
        }
    }
}

// ---------------------------------------------------------------------------
// inputs (metadata order): h f32[100000,64], src [1.6M] (i32), dst [1.6M]
// (i32), W f32[64,128], b f32[64]; output f32[100000,64]
// ---------------------------------------------------------------------------
extern "C" void kernel_launch(void* const* d_in, const int* in_sizes, int n_in,
                              void* d_out, int out_size) {
    const float* h = (const float*)d_in[0];
    const void* src = d_in[1];
    const void* dst = d_in[2];
    const float* W = (const float*)d_in[3];
    const float* b = (const float*)d_in[4];
    float* out = (float*)d_out;

    const int EB = (N_EDGES + 255) / 256;  // 6250

    zero_kernel<<<256, 256>>>(src);
    hist_kernel<<<EB, 256>>>(dst);
    scan1_kernel<<<NB_SCAN, 256>>>();
    scan2_kernel<<<1, 512>>>();
    scan3_kernel<<<NB_SCAN, 256>>>();
    fill_kernel<<<EB, 256>>>(src, dst);
    aggregate_kernel<<<(N_NODES * 32 + 255) / 256, 256>>>(h);
    gemm_kernel<<<(N_NODES + TILE_N - 1) / TILE_N, 128>>>(h, W, b, out);
}

// round 14
// speedup vs baseline: 2.2677x; 1.1071x over previous
#include <cuda_runtime.h>

#define N_NODES 100000
#define N_EDGES 1600000
#define F 64
#define TWOF 128
#define NB_SCAN ((N_NODES + 255) / 256)   // 391 scan blocks
#define GEMM_NB ((N_NODES + 127) / 128)   // 782 gemm blocks

// ---------------------------------------------------------------------------
// Scratch (device globals; allocations are forbidden)
// ---------------------------------------------------------------------------
__device__ int    g_is32;                // 1 if src/dst are int32, 0 if int64
__device__ int    g_deg[N_NODES];        // per-node in-degree
__device__ int    g_off[N_NODES];        // block-LOCAL exclusive prefix
__device__ int    g_cursor[N_NODES];     // fill cursors (seeded local prefix)
__device__ int    g_part[NB_SCAN];       // exclusive block bases (after scan2)
__device__ int    g_esrc[N_EDGES];       // bucketed source-node ids (CSR adj)
__device__ float4 g_hN[(size_t)N_NODES * 16];  // mean-aggregated features [N,64]

// Index load that works for either dtype.
__device__ __forceinline__ int load_id(const void* p, int e, int is32) {
    return is32 ? ((const int*)p)[e] : (int)((const long long*)p)[e];
}

// Packed fp32x2 FMA (sm_103a): d = a*b + d elementwise on 2 packed floats.
__device__ __forceinline__ void ffma2(unsigned long long& d,
                                      unsigned long long a,
                                      unsigned long long b) {
    asm("fma.rn.f32x2 %0, %1, %2, %0;" : "+l"(d) : "l"(a), "l"(b));
}

// ---------------------------------------------------------------------------
// 1) zero degree counters + dtype detection (validated: rel_err 2.8e-7).
// ---------------------------------------------------------------------------
__global__ void zero_kernel(const void* __restrict__ srcbuf) {
    int stride = gridDim.x * blockDim.x;
    for (int i = blockIdx.x * blockDim.x + threadIdx.x; i < N_NODES; i += stride)
        g_deg[i] = 0;

    if (blockIdx.x == 0 && threadIdx.x < 32) {
        const int* p = (const int*)srcbuf;
        int acc = 0;
        for (int i = threadIdx.x; i < 2048; i += 32)
            acc |= __ldg(p + 2 * i + 1);
#pragma unroll
        for (int d = 16; d > 0; d >>= 1)
            acc |= __shfl_xor_sync(0xffffffffu, acc, d);
        if (threadIdx.x == 0) g_is32 = (acc != 0) ? 1 : 0;
    }
}

// ---------------------------------------------------------------------------
// 2) degree histogram (grid-stride; guarded)
// ---------------------------------------------------------------------------
__global__ __launch_bounds__(256) void hist_kernel(const void* __restrict__ dst) {
    const int is32 = g_is32;
    const int stride = gridDim.x * blockDim.x;
    for (int e = blockIdx.x * blockDim.x + threadIdx.x; e < N_EDGES; e += stride) {
        int d = load_id(dst, e, is32);
        if ((unsigned)d < N_NODES) atomicAdd(&g_deg[d], 1);
    }
}

// ---------------------------------------------------------------------------
// 3a) scan phase 1: block-local exclusive scan of 256 degrees.
//     g_off/g_cursor get the LOCAL prefix; g_part the block total.
//     (Consumers add g_part[i>>8]; scan3 kernel eliminated.)
// ---------------------------------------------------------------------------
__global__ __launch_bounds__(256) void scan1_kernel() {
    __shared__ int s[256];
    int t = threadIdx.x;
    int i = blockIdx.x * 256 + t;
    int v = (i < N_NODES) ? g_deg[i] : 0;
    s[t] = v;
    __syncthreads();
#pragma unroll
    for (int d = 1; d < 256; d <<= 1) {
        int x = (t >= d) ? s[t - d] : 0;
        __syncthreads();
        s[t] += x;
        __syncthreads();
    }
    if (i < N_NODES) {
        int loc = s[t] - v;   // exclusive local prefix
        g_off[i] = loc;
        g_cursor[i] = loc;
    }
    if (t == 255) g_part[blockIdx.x] = s[255];
}

// ---------------------------------------------------------------------------
// 3b) scan phase 2: exclusive scan of the 391 block totals (one tiny block).
// ---------------------------------------------------------------------------
__global__ __launch_bounds__(512) void scan2_kernel() {
    __shared__ int s[512];
    int t = threadIdx.x;
    int v = (t < NB_SCAN) ? g_part[t] : 0;
    s[t] = v;
    __syncthreads();
#pragma unroll
    for (int d = 1; d < 512; d <<= 1) {
        int x = (t >= d) ? s[t - d] : 0;
        __syncthreads();
        s[t] += x;
        __syncthreads();
    }
    if (t < NB_SCAN) g_part[t] = s[t] - v;      // exclusive block base
}

// ---------------------------------------------------------------------------
// 4) bucket fill: absolute slot = local cursor + block base.
// ---------------------------------------------------------------------------
__global__ __launch_bounds__(256) void fill_kernel(const void* __restrict__ src,
                                                   const void* __restrict__ dst) {
    const int is32 = g_is32;
    const int stride = gridDim.x * blockDim.x;
    for (int e = blockIdx.x * blockDim.x + threadIdx.x; e < N_EDGES; e += stride) {
        int d = load_id(dst, e, is32);
        int sv = load_id(src, e, is32);
        if ((unsigned)d >= N_NODES || (unsigned)sv >= N_NODES) continue;
        int pos = atomicAdd(&g_cursor[d], 1);
        g_esrc[pos + __ldg(g_part + (d >> 8))] = sv;
    }
}

// ---------------------------------------------------------------------------
// 5) pull aggregation: warp per node, lane owns 2 columns, 8-edge unroll.
// ---------------------------------------------------------------------------
__global__ __launch_bounds__(256) void aggregate_kernel(const float* __restrict__ h) {
    int node = (blockIdx.x * blockDim.x + threadIdx.x) >> 5;
    if (node >= N_NODES) return;
    int lane = threadIdx.x & 31;

    int off = g_off[node] + __ldg(g_part + (node >> 8));
    int deg = g_deg[node];
    const float2* h2 = reinterpret_cast<const float2*>(h);

    float ax = 0.f, ay = 0.f;
    int i = 0;
    for (; i + 8 <= deg; i += 8) {
        int s[8];
#pragma unroll
        for (int u = 0; u < 8; u++) s[u] = __ldg(g_esrc + off + i + u);
        float2 v[8];
#pragma unroll
        for (int u = 0; u < 8; u++) v[u] = __ldg(h2 + s[u] * 32 + lane);
#pragma unroll
        for (int u = 0; u < 8; u++) { ax += v[u].x; ay += v[u].y; }
    }
    for (; i < deg; i++) {
        int s0 = __ldg(g_esrc + off + i);
        float2 v0 = __ldg(h2 + s0 * 32 + lane);
        ax += v0.x;
        ay += v0.y;
    }

    float inv = 1.0f / (float)max(deg, 1);
    float2 r; r.x = ax * inv; r.y = ay * inv;
    reinterpret_cast<float2*>(g_hN)[node * 32 + lane] = r;
}

// ---------------------------------------------------------------------------
// 6) GEMM v2: concat + GEMM + bias with packed f32x2 FMA.
//    Block: 128 nodes x 64 outs, 128 threads, per-thread 8x8 (nodes tm+16r,
//    outs tn+8c). K in two 64-wide phases: phase0 = h, phase1 = hN (concat
//    is free). smem 48KB: sH 128x64 (32KB) + sW 64x64 (16KB), 16B-chunk
//    XOR swizzle (chunk = k4 ^ (row & 15)) -> conflict-free inner loads.
//    Accumulators are f32x2 packed over k-parity; fp32 math throughout.
// ---------------------------------------------------------------------------
__global__ __launch_bounds__(128) void gemm_kernel(
    const float* __restrict__ h,
    const float* __restrict__ W,
    const float* __restrict__ b,
    float* __restrict__ out) {
    __shared__ float sH[128 * F];   // 32KB
    __shared__ float sW[64 * F];    // 16KB

    const int t = threadIdx.x;
    const int node0 = blockIdx.x * 128;
    const int tm = t & 15;          // node lane: rows tm + 16*r
    const int tn = t >> 4;          // out lane:  cols tn + 8*c

    unsigned long long acc[8][8];
#pragma unroll
    for (int r = 0; r < 8; r++)
#pragma unroll
        for (int c = 0; c < 8; c++) acc[r][c] = 0ull;

    const float4* h4 = reinterpret_cast<const float4*>(h);
    const float4* w4 = reinterpret_cast<const float4*>(W);
    float4* sH4 = reinterpret_cast<float4*>(sH);
    float4* sW4 = reinterpret_cast<float4*>(sW);

#pragma unroll
    for (int p = 0; p < 2; p++) {
        if (p) __syncthreads();  // protect smem reuse between phases
        // sW: 64 rows x 16 chunks; W row j has 32 float4, phase offset p*16
        for (int idx = t; idx < 64 * 16; idx += 128) {
            int j = idx >> 4, k4 = idx & 15;
            float4 w = __ldg(w4 + j * 32 + p * 16 + k4);
            sW4[j * 16 + (k4 ^ (j & 15))] = w;
        }
        // sH: 128 rows x 16 chunks; phase0 = h row, phase1 = hN row
        for (int idx = t; idx < 128 * 16; idx += 128) {
            int r = idx >> 4, k4 = idx & 15;
            int n = node0 + r;
            float4 v = make_float4(0.f, 0.f, 0.f, 0.f);
            if (n < N_NODES)
                v = p ? g_hN[(size_t)n * 16 + k4] : __ldg(h4 + n * 16 + k4);
            sH4[r * 16 + (k4 ^ (r & 15))] = v;
        }
        __syncthreads();

#pragma unroll
        for (int k4 = 0; k4 < 16; k4++) {
            ulonglong2 hv[8];
            const int hc = k4 ^ tm;          // (tm+16r) & 15 == tm
#pragma unroll
            for (int r = 0; r < 8; r++)
                hv[r] = *reinterpret_cast<const ulonglong2*>(
                    sH4 + (tm + 16 * r) * 16 + hc);
#pragma unroll
            for (int c = 0; c < 8; c++) {
                int j = tn + 8 * c;
                ulonglong2 wv = *reinterpret_cast<const ulonglong2*>(
                    sW4 + j * 16 + (k4 ^ (j & 15)));
#pragma unroll
                for (int r = 0; r < 8; r++) {
                    ffma2(acc[r][c], hv[r].x, wv.x);
                    ffma2(acc[r][c], hv[r].y, wv.y);
                }
            }
        }
    }

    // epilogue: reduce k-parity halves, add bias, store
    float bias[8];
#pragma unroll
    for (int c = 0; c < 8; c++) bias[c] = __ldg(b + tn + 8 * c);
#pragma unroll
    for (int r = 0; r < 8; r++) {
        int n = node0 + tm + 16 * r;
        if (n < N_NODES) {
#pragma unroll
            for (int c = 0; c < 8; c++) {
                float2 v = *reinterpret_cast<float2*>(&acc[r][c]);
                out[(size_t)n * F + tn + 8 * c] = v.x + v.y + bias[c];
            }
        }
    }
}

// ---------------------------------------------------------------------------
// inputs: h f32[100000,64], src i32/i64[1.6M], dst i32/i64[1.6M],
//         W f32[64,128], b f32[64]; output f32[100000,64]
// ---------------------------------------------------------------------------
extern "C" void kernel_launch(void* const* d_in, const int* in_sizes, int n_in,
                              void* d_out, int out_size) {
    const float* h = (const float*)d_in[0];
    const void* src = d_in[1];
    const void* dst = d_in[2];
    const float* W = (const float*)d_in[3];
    const float* b = (const float*)d_in[4];
    float* out = (float*)d_out;

    const int EB = (N_EDGES + 255) / 256;  // 6250

    zero_kernel<<<256, 256>>>(src);
    hist_kernel<<<EB, 256>>>(dst);
    scan1_kernel<<<NB_SCAN, 256>>>();
    scan2_kernel<<<1, 512>>>();
    fill_kernel<<<EB, 256>>>(src, dst);
    aggregate_kernel<<<(N_NODES * 32 + 255) / 256, 256>>>(h);
    gemm_kernel<<<GEMM_NB, 128>>>(h, W, b, out);
}